// round 1
// baseline (speedup 1.0000x reference)
#include <cuda_runtime.h>

// MoE hash-routed layer, GB300 round-1 baseline.
// Routing -> per-expert buckets -> grouped SGEMM1 (x@W1+b1, relu) -> scratch H
// -> grouped SGEMM2 (H@W2), 0.5*(y+b2) atomically scattered to out.

#define D         1024
#define DFF       4096
#define NE        8
#define T_MAX     4096
#define BM        128
#define BN        128
#define BK        8
#define MAX_TILES 72   // sum_e ceil(cnt_e/128) <= 8192/128 + 7 = 71

__device__ int   g_cnt[NE];
__device__ int   g_bucket[NE * T_MAX];
__device__ int   g_tile_e[MAX_TILES];
__device__ int   g_tile_m0[MAX_TILES];
__device__ float g_H[(size_t)MAX_TILES * BM * DFF];   // ~151 MB scratch

__global__ void zero_cnt_kernel() {
    if (threadIdx.x < NE) g_cnt[threadIdx.x] = 0;
}

__global__ void route_kernel(const float* __restrict__ x, int T) {
    int t = blockIdx.x * blockDim.x + threadIdx.x;
    if (t >= T) return;
    // h = jnp.mod((x0+x1).astype(int32), 8): trunc-toward-zero cast, Python mod
    float s = x[(size_t)t * D] + x[(size_t)t * D + 1];
    int i = (int)s;
    int h = ((i % NE) + NE) % NE;
    int e0 = h;
    int e1 = (h + 1) & (NE - 1);
    int p0 = atomicAdd(&g_cnt[e0], 1);
    g_bucket[e0 * T_MAX + p0] = t;
    int p1 = atomicAdd(&g_cnt[e1], 1);
    g_bucket[e1 * T_MAX + p1] = t;
}

__global__ void tilemap_kernel() {
    if (threadIdx.x != 0) return;
    int tt = 0;
    for (int e = 0; e < NE; e++) {
        int nt = (g_cnt[e] + BM - 1) / BM;
        for (int i = 0; i < nt && tt < MAX_TILES; i++) {
            g_tile_e[tt]  = e;
            g_tile_m0[tt] = i * BM;
            tt++;
        }
    }
    for (; tt < MAX_TILES; tt++) g_tile_e[tt] = -1;
}

// ---------------- GEMM1: H[slot, n] = relu(x[tok] @ W1[e] + b1[e]) ----------------
__global__ __launch_bounds__(256)
void gemm1_kernel(const float* __restrict__ x, const float* __restrict__ W1,
                  const float* __restrict__ b1) {
    int tt = blockIdx.y;
    int e  = g_tile_e[tt];
    if (e < 0) return;
    int m0  = g_tile_m0[tt];
    int cnt = g_cnt[e];
    int n0  = blockIdx.x * BN;

    __shared__ float As[BK][BM];
    __shared__ float Bs[BK][BN];
    __shared__ int   s_tok[BM];

    int tid = threadIdx.x;
    if (tid < BM) {
        int m = m0 + tid;
        s_tok[tid] = (m < cnt) ? g_bucket[e * T_MAX + m] : -1;
    }
    __syncthreads();

    const float* Wb = W1 + (size_t)e * D * DFF + n0;

    int trow = (tid >> 4) << 3;   // 0..120
    int tcol = (tid & 15) << 3;   // 0..120

    float acc[8][8];
    #pragma unroll
    for (int i = 0; i < 8; i++)
        #pragma unroll
        for (int j = 0; j < 8; j++) acc[i][j] = 0.f;

    // A-loader: 2 threads per row (k halves), gathered rows
    int arow = tid >> 1;
    int ak   = (tid & 1) << 2;
    int atok = s_tok[arow];
    bool avalid = (atok >= 0);
    const float* aptr = x + (size_t)(avalid ? atok : 0) * D + ak;

    // B-loader: 8 k-rows x 32 threads, float4 along n
    int brow = tid >> 5;
    int bcol = (tid & 31) << 2;
    const float* bptr = Wb + (size_t)brow * DFF + bcol;

    for (int k0 = 0; k0 < D; k0 += BK) {
        float4 av = make_float4(0.f, 0.f, 0.f, 0.f);
        if (avalid) av = *(const float4*)(aptr + k0);
        float4 bv = *(const float4*)(bptr + (size_t)k0 * DFF);
        __syncthreads();
        As[ak + 0][arow] = av.x;
        As[ak + 1][arow] = av.y;
        As[ak + 2][arow] = av.z;
        As[ak + 3][arow] = av.w;
        *(float4*)&Bs[brow][bcol] = bv;
        __syncthreads();
        #pragma unroll
        for (int kk = 0; kk < BK; kk++) {
            float4 a0 = *(const float4*)&As[kk][trow];
            float4 a1 = *(const float4*)&As[kk][trow + 4];
            float4 b0 = *(const float4*)&Bs[kk][tcol];
            float4 b1r = *(const float4*)&Bs[kk][tcol + 4];
            float a[8] = {a0.x, a0.y, a0.z, a0.w, a1.x, a1.y, a1.z, a1.w};
            float b[8] = {b0.x, b0.y, b0.z, b0.w, b1r.x, b1r.y, b1r.z, b1r.w};
            #pragma unroll
            for (int i = 0; i < 8; i++)
                #pragma unroll
                for (int j = 0; j < 8; j++)
                    acc[i][j] = fmaf(a[i], b[j], acc[i][j]);
        }
    }

    float bias[8];
    #pragma unroll
    for (int j = 0; j < 8; j++) bias[j] = b1[(size_t)e * DFF + n0 + tcol + j];

    #pragma unroll
    for (int i = 0; i < 8; i++) {
        int m = m0 + trow + i;
        if (m < cnt) {
            float* hrow = g_H + ((size_t)tt * BM + trow + i) * DFF + n0 + tcol;
            float v[8];
            #pragma unroll
            for (int j = 0; j < 8; j++) v[j] = fmaxf(acc[i][j] + bias[j], 0.f);
            *(float4*)(hrow)     = make_float4(v[0], v[1], v[2], v[3]);
            *(float4*)(hrow + 4) = make_float4(v[4], v[5], v[6], v[7]);
        }
    }
}

// ---------------- GEMM2: out[tok] += 0.5*(H[slot] @ W2[e] + b2[e]) ----------------
__global__ __launch_bounds__(256)
void gemm2_kernel(const float* __restrict__ W2, const float* __restrict__ b2,
                  float* __restrict__ out) {
    int tt = blockIdx.y;
    int e  = g_tile_e[tt];
    if (e < 0) return;
    int m0  = g_tile_m0[tt];
    int cnt = g_cnt[e];
    int n0  = blockIdx.x * BN;

    __shared__ float As[BK][BM];
    __shared__ float Bs[BK][BN];
    __shared__ int   s_tok[BM];

    int tid = threadIdx.x;
    if (tid < BM) {
        int m = m0 + tid;
        s_tok[tid] = (m < cnt) ? g_bucket[e * T_MAX + m] : -1;
    }
    __syncthreads();

    const float* Wb = W2 + (size_t)e * DFF * D + n0;

    int trow = (tid >> 4) << 3;
    int tcol = (tid & 15) << 3;

    float acc[8][8];
    #pragma unroll
    for (int i = 0; i < 8; i++)
        #pragma unroll
        for (int j = 0; j < 8; j++) acc[i][j] = 0.f;

    int arow = tid >> 1;
    int ak   = (tid & 1) << 2;
    const float* aptr = g_H + ((size_t)tt * BM + arow) * DFF + ak;

    int brow = tid >> 5;
    int bcol = (tid & 31) << 2;
    const float* bptr = Wb + (size_t)brow * D + bcol;

    for (int k0 = 0; k0 < DFF; k0 += BK) {
        float4 av = *(const float4*)(aptr + k0);
        float4 bv = *(const float4*)(bptr + (size_t)k0 * D);
        __syncthreads();
        As[ak + 0][arow] = av.x;
        As[ak + 1][arow] = av.y;
        As[ak + 2][arow] = av.z;
        As[ak + 3][arow] = av.w;
        *(float4*)&Bs[brow][bcol] = bv;
        __syncthreads();
        #pragma unroll
        for (int kk = 0; kk < BK; kk++) {
            float4 a0 = *(const float4*)&As[kk][trow];
            float4 a1 = *(const float4*)&As[kk][trow + 4];
            float4 b0 = *(const float4*)&Bs[kk][tcol];
            float4 b1r = *(const float4*)&Bs[kk][tcol + 4];
            float a[8] = {a0.x, a0.y, a0.z, a0.w, a1.x, a1.y, a1.z, a1.w};
            float b[8] = {b0.x, b0.y, b0.z, b0.w, b1r.x, b1r.y, b1r.z, b1r.w};
            #pragma unroll
            for (int i = 0; i < 8; i++)
                #pragma unroll
                for (int j = 0; j < 8; j++)
                    acc[i][j] = fmaf(a[i], b[j], acc[i][j]);
        }
    }

    float bias[8];
    #pragma unroll
    for (int j = 0; j < 8; j++) bias[j] = b2[(size_t)e * D + n0 + tcol + j];

    #pragma unroll
    for (int i = 0; i < 8; i++) {
        int tok = s_tok[trow + i];
        if (tok >= 0) {
            float* orow = out + (size_t)tok * D + n0 + tcol;
            #pragma unroll
            for (int j = 0; j < 8; j++)
                atomicAdd(&orow[j], 0.5f * (acc[i][j] + bias[j]));
        }
    }
}

extern "C" void kernel_launch(void* const* d_in, const int* in_sizes, int n_in,
                              void* d_out, int out_size) {
    const float* x  = (const float*)d_in[0];
    const float* W1 = (const float*)d_in[1];
    const float* b1 = (const float*)d_in[2];
    const float* W2 = (const float*)d_in[3];
    const float* b2 = (const float*)d_in[4];
    float* out = (float*)d_out;

    int T = in_sizes[0] / D;
    if (T > T_MAX) T = T_MAX;

    cudaMemsetAsync(out, 0, (size_t)out_size * sizeof(float));
    zero_cnt_kernel<<<1, 32>>>();
    route_kernel<<<(T + 255) / 256, 256>>>(x, T);
    tilemap_kernel<<<1, 32>>>();
    gemm1_kernel<<<dim3(DFF / BN, MAX_TILES), 256>>>(x, W1, b1);
    gemm2_kernel<<<dim3(D / BN, MAX_TILES), 256>>>(W2, b2, out);
}

// round 5
// speedup vs baseline: 2.4310x; 2.4310x over previous
#include <cuda_runtime.h>
#include <cuda_bf16.h>
#include <cstdint>

#define D_DIM     1024
#define DFF       4096
#define NE        8
#define T_MAX     4096
#define BM        128
#define BN        128
#define KC        32
#define MAX_TILES 72
#define ROWB      80            // padded row stride bytes (32 bf16 data + 8 pad)
#define SECB      (128 * ROWB)  // 10240 bytes per section
#define SMEMB     (4 * SECB)    // 40960 bytes, static

// ---------------- device scratch (NEVER passed as kernel args) ----------------
__device__ int   g_cnt[NE];
__device__ int   g_bucket[NE * T_MAX];
__device__ int2  g_pos[T_MAX];
__device__ int   g_tile_e[MAX_TILES];
__device__ int   g_tile_m0[MAX_TILES];
__device__ int   g_ebase[NE];

__device__ __nv_bfloat16 g_Ah[(size_t)MAX_TILES * BM * D_DIM];
__device__ __nv_bfloat16 g_Al[(size_t)MAX_TILES * BM * D_DIM];
__device__ __nv_bfloat16 g_W1t_h[(size_t)NE * DFF * D_DIM];
__device__ __nv_bfloat16 g_W1t_l[(size_t)NE * DFF * D_DIM];
__device__ __nv_bfloat16 g_W2t_h[(size_t)NE * D_DIM * DFF];
__device__ __nv_bfloat16 g_W2t_l[(size_t)NE * D_DIM * DFF];
__device__ __nv_bfloat16 g_Hh[(size_t)MAX_TILES * BM * DFF];
__device__ __nv_bfloat16 g_Hl[(size_t)MAX_TILES * BM * DFF];
__device__ float         g_part[(size_t)MAX_TILES * BM * D_DIM];

// ---------------- helpers ----------------
__device__ __forceinline__ uint32_t smem_u32(const void* p) {
    uint32_t a;
    asm("{ .reg .u64 t; cvta.to.shared.u64 t, %1; cvt.u32.u64 %0, t; }" : "=r"(a) : "l"(p));
    return a;
}
__device__ __forceinline__ uint32_t pack_bf2(float a, float b) {
    __nv_bfloat162 t = __floats2bfloat162_rn(a, b);
    return *reinterpret_cast<uint32_t*>(&t);
}
__device__ __forceinline__ void ldm_x4(uint32_t* r, uint32_t addr) {
    asm volatile("ldmatrix.sync.aligned.m8n8.x4.shared.b16 {%0,%1,%2,%3}, [%4];"
                 : "=r"(r[0]), "=r"(r[1]), "=r"(r[2]), "=r"(r[3]) : "r"(addr));
}
__device__ __forceinline__ void mma_bf16(float* c, const uint32_t* a, const uint32_t* b) {
    asm volatile("mma.sync.aligned.m16n8k16.row.col.f32.bf16.bf16.f32 "
                 "{%0,%1,%2,%3}, {%4,%5,%6,%7}, {%8,%9}, {%0,%1,%2,%3};"
                 : "+f"(c[0]), "+f"(c[1]), "+f"(c[2]), "+f"(c[3])
                 : "r"(a[0]), "r"(a[1]), "r"(a[2]), "r"(a[3]), "r"(b[0]), "r"(b[1]));
}

// ---------------- routing ----------------
__global__ void zero_cnt_kernel() { if (threadIdx.x < NE) g_cnt[threadIdx.x] = 0; }

__global__ void route_kernel(const float* __restrict__ x, int T) {
    int t = blockIdx.x * blockDim.x + threadIdx.x;
    if (t >= T) return;
    float s = x[(size_t)t * D_DIM] + x[(size_t)t * D_DIM + 1];
    int i = (int)s;
    int h = ((i % NE) + NE) % NE;
    int e0 = h, e1 = (h + 1) & (NE - 1);
    int p0 = atomicAdd(&g_cnt[e0], 1);
    g_bucket[e0 * T_MAX + p0] = t;
    int p1 = atomicAdd(&g_cnt[e1], 1);
    g_bucket[e1 * T_MAX + p1] = t;
    g_pos[t] = make_int2(p0, p1);
}

__global__ void tilemap_kernel() {
    if (threadIdx.x != 0) return;
    int tt = 0;
    for (int e = 0; e < NE; e++) {
        g_ebase[e] = tt * BM;
        int nt = (g_cnt[e] + BM - 1) / BM;
        for (int i = 0; i < nt && tt < MAX_TILES; i++) {
            g_tile_e[tt] = e; g_tile_m0[tt] = i * BM; tt++;
        }
    }
    for (; tt < MAX_TILES; tt++) g_tile_e[tt] = -1;
}

// ---------------- gather + split-convert A ----------------
__global__ __launch_bounds__(256)
void convertA_kernel(const float* __restrict__ x) {
    int tt = blockIdx.x;
    int e = g_tile_e[tt];
    if (e < 0) return;
    int m0 = g_tile_m0[tt], cnt = g_cnt[e];
    int sub = blockIdx.y;
    for (int idx = threadIdx.x; idx < 32 * 256; idx += 256) {
        int r = sub * 32 + (idx >> 8);
        int c4 = (idx & 255) * 4;
        int m = m0 + r;
        int tok = (m < cnt) ? g_bucket[e * T_MAX + m] : -1;
        float4 v = make_float4(0.f, 0.f, 0.f, 0.f);
        if (tok >= 0) v = *(const float4*)(x + (size_t)tok * D_DIM + c4);
        float hx = __bfloat162float(__float2bfloat16_rn(v.x));
        float hy = __bfloat162float(__float2bfloat16_rn(v.y));
        float hz = __bfloat162float(__float2bfloat16_rn(v.z));
        float hw = __bfloat162float(__float2bfloat16_rn(v.w));
        uint2 hp, lp;
        hp.x = pack_bf2(v.x, v.y); hp.y = pack_bf2(v.z, v.w);
        lp.x = pack_bf2(v.x - hx, v.y - hy); lp.y = pack_bf2(v.z - hz, v.w - hw);
        size_t off = ((size_t)tt * BM + r) * D_DIM + c4;
        *(uint2*)(g_Ah + off) = hp;
        *(uint2*)(g_Al + off) = lp;
    }
}

// ---- transpose + split-convert W: [E][K][N] f32 -> [E][N][K] bf16 hi/lo ----
// WHICH selects destination globals INSIDE device code (no __device__ ptr args).
template<int WHICH>
__global__ __launch_bounds__(256)
void convertW_kernel(const float* __restrict__ W) {
    constexpr int K = (WHICH == 1) ? D_DIM : DFF;
    constexpr int N = (WHICH == 1) ? DFF : D_DIM;
    __nv_bfloat16* Dh = (WHICH == 1) ? g_W1t_h : g_W2t_h;
    __nv_bfloat16* Dl = (WHICH == 1) ? g_W1t_l : g_W2t_l;

    __shared__ float ts[64][33];
    int e = blockIdx.z;
    const float* We = W + (size_t)e * K * N;
    int nb = blockIdx.x * 32, kb = blockIdx.y * 64;
    int tx = threadIdx.x, ty = threadIdx.y;
    #pragma unroll
    for (int i = 0; i < 8; i++) {
        int kl = ty + i * 8;
        ts[kl][tx] = We[(size_t)(kb + kl) * N + nb + tx];
    }
    __syncthreads();
    #pragma unroll
    for (int i = 0; i < 4; i++) {
        int nl = ty + i * 8;
        float v0 = ts[2 * tx][nl], v1 = ts[2 * tx + 1][nl];
        float h0 = __bfloat162float(__float2bfloat16_rn(v0));
        float h1 = __bfloat162float(__float2bfloat16_rn(v1));
        size_t off = ((size_t)e * N + nb + nl) * K + kb + 2 * tx;
        *(uint32_t*)(Dh + off) = pack_bf2(v0, v1);
        *(uint32_t*)(Dl + off) = pack_bf2(v0 - h0, v1 - h1);
    }
}

// ---------------- HMMA grouped GEMM (split-bf16, 3 passes) ----------------
// Register-staged pipeline: global loads for chunk c+1 issue before MMA of chunk c.
// MODE 1: H = relu(x@W1 + b1) -> bf16 hi/lo.   MODE 2: part = H@W2 (fp32).
template<int KT, int MODE, int NTOT>
__global__ __launch_bounds__(256, 1)
void moe_gemm_hmma(const float* __restrict__ bias) {
    __shared__ __align__(128) char smem[SMEMB];

    int tt = blockIdx.y;
    int e = g_tile_e[tt];
    if (e < 0) return;
    int n0 = blockIdx.x * BN;

    uint32_t sb = smem_u32(smem);
    int tid = threadIdx.x, lane = tid & 31, wid = tid >> 5;
    int wm0 = (wid & 1) * 64;          // 2 warps along M
    int wn0 = (wid >> 1) * 32;         // 4 warps along N

    const __nv_bfloat16 *Ah, *Al, *Bh, *Bl;
    if (MODE == 1) { Ah = g_Ah; Al = g_Al; Bh = g_W1t_h; Bl = g_W1t_l; }
    else           { Ah = g_Hh; Al = g_Hl; Bh = g_W2t_h; Bl = g_W2t_l; }
    Ah += (size_t)tt * BM * KT;  Al += (size_t)tt * BM * KT;
    size_t boff = ((size_t)e * NTOT + n0) * KT;
    Bh += boff;  Bl += boff;

    // per-lane ldmatrix geometry (padded rows, no swizzle; all addrs 16B aligned)
    int m4 = lane >> 3;
    int r8 = lane & 7;
    int aHalf = (m4 >> 1) * 16;
    int aRowLoc = (m4 & 1) * 8 + r8;
    int bHalf = (m4 & 1) * 16;
    int bRowLoc = (m4 >> 1) * 8 + r8;

    uint32_t aCore[4], bCore[2];
    #pragma unroll
    for (int mi = 0; mi < 4; mi++) aCore[mi] = (uint32_t)((wm0 + 16 * mi + aRowLoc) * ROWB);
    #pragma unroll
    for (int p = 0; p < 2; p++)   bCore[p]  = (uint32_t)((wn0 + 16 * p + bRowLoc) * ROWB);

    // loader geometry: 8 uint4 per thread per chunk; sec = i>>1
    const __nv_bfloat16* secp[4] = { Ah, Al, Bh, Bl };
    int lrow[8], lc16[8];
    uint32_t ldst[8];
    #pragma unroll
    for (int i = 0; i < 8; i++) {
        int idx = tid + (i & 1) * 256;
        int sec = i >> 1;
        lrow[i] = idx >> 2;
        lc16[i] = idx & 3;
        ldst[i] = (uint32_t)(sec * SECB + lrow[i] * ROWB + lc16[i] * 16);
    }

    float acc[4][4][4];
    #pragma unroll
    for (int i = 0; i < 4; i++)
        #pragma unroll
        for (int j = 0; j < 4; j++)
            #pragma unroll
            for (int q = 0; q < 4; q++) acc[i][j][q] = 0.f;

    const int NC = KT / KC;

    // preload chunk 0 into registers
    uint4 v[8];
    #pragma unroll
    for (int i = 0; i < 8; i++)
        v[i] = *(const uint4*)(secp[i >> 1] + (size_t)lrow[i] * KT + lc16[i] * 8);

    for (int c = 0; c < NC; c++) {
        __syncthreads();   // previous compute done before overwrite
        #pragma unroll
        for (int i = 0; i < 8; i++) *(uint4*)(smem + ldst[i]) = v[i];
        __syncthreads();

        if (c + 1 < NC) {
            int k0 = (c + 1) * KC;
            #pragma unroll
            for (int i = 0; i < 8; i++)
                v[i] = *(const uint4*)(secp[i >> 1] + (size_t)lrow[i] * KT + k0 + lc16[i] * 8);
        }

        uint32_t sAh = sb, sAl = sb + SECB, sBh = sb + 2 * SECB, sBl = sb + 3 * SECB;
        #pragma unroll
        for (int kk = 0; kk < 2; kk++) {
            uint32_t aoff = (uint32_t)(kk * 32 + aHalf);
            uint32_t boffc = (uint32_t)(kk * 32 + bHalf);
            uint32_t ah[4][4], al[4][4], bhf[4][2], blf[4][2];
            #pragma unroll
            for (int mi = 0; mi < 4; mi++) {
                ldm_x4(ah[mi], sAh + aCore[mi] + aoff);
                ldm_x4(al[mi], sAl + aCore[mi] + aoff);
            }
            #pragma unroll
            for (int p = 0; p < 2; p++) {
                uint32_t r[4];
                ldm_x4(r, sBh + bCore[p] + boffc);
                bhf[2 * p][0] = r[0]; bhf[2 * p][1] = r[1];
                bhf[2 * p + 1][0] = r[2]; bhf[2 * p + 1][1] = r[3];
                ldm_x4(r, sBl + bCore[p] + boffc);
                blf[2 * p][0] = r[0]; blf[2 * p][1] = r[1];
                blf[2 * p + 1][0] = r[2]; blf[2 * p + 1][1] = r[3];
            }
            #pragma unroll
            for (int mi = 0; mi < 4; mi++)
                #pragma unroll
                for (int ni = 0; ni < 4; ni++) {
                    mma_bf16(acc[mi][ni], ah[mi], bhf[ni]);
                    mma_bf16(acc[mi][ni], al[mi], bhf[ni]);
                    mma_bf16(acc[mi][ni], ah[mi], blf[ni]);
                }
        }
    }

    // ---------------- epilogue ----------------
    int trow = lane >> 2;
    int tcol = (lane & 3) * 2;
    #pragma unroll
    for (int ni = 0; ni < 4; ni++) {
        int col = wn0 + 8 * ni + tcol;
        float b0 = 0.f, b1 = 0.f;
        if (MODE == 1) {
            b0 = __ldg(bias + (size_t)e * DFF + n0 + col);
            b1 = __ldg(bias + (size_t)e * DFF + n0 + col + 1);
        }
        #pragma unroll
        for (int mi = 0; mi < 4; mi++) {
            float* cc = acc[mi][ni];
            #pragma unroll
            for (int half = 0; half < 2; half++) {
                int row = wm0 + 16 * mi + trow + half * 8;
                size_t slot = (size_t)tt * BM + row;
                float v0 = cc[2 * half], v1 = cc[2 * half + 1];
                if (MODE == 1) {
                    v0 = fmaxf(v0 + b0, 0.f);
                    v1 = fmaxf(v1 + b1, 0.f);
                    float h0 = __bfloat162float(__float2bfloat16_rn(v0));
                    float h1 = __bfloat162float(__float2bfloat16_rn(v1));
                    *(uint32_t*)(g_Hh + slot * DFF + n0 + col) = pack_bf2(v0, v1);
                    *(uint32_t*)(g_Hl + slot * DFF + n0 + col) = pack_bf2(v0 - h0, v1 - h1);
                } else {
                    *(float2*)(g_part + slot * D_DIM + n0 + col) = make_float2(v0, v1);
                }
            }
        }
    }
}

// ---------------- combine: out = 0.5*(p0 + p1 + b2[e0] + b2[e1]) ----------------
__global__ __launch_bounds__(256)
void combine_kernel(const float* __restrict__ x, const float* __restrict__ b2,
                    float* __restrict__ out) {
    int t = blockIdx.x;
    float s = x[(size_t)t * D_DIM] + x[(size_t)t * D_DIM + 1];
    int i = (int)s;
    int h = ((i % NE) + NE) % NE;
    int e0 = h, e1 = (h + 1) & (NE - 1);
    int2 pp = g_pos[t];
    const float* p0 = g_part + (size_t)(g_ebase[e0] + pp.x) * D_DIM;
    const float* p1 = g_part + (size_t)(g_ebase[e1] + pp.y) * D_DIM;
    const float* ba = b2 + (size_t)e0 * D_DIM;
    const float* bb = b2 + (size_t)e1 * D_DIM;
    int c = threadIdx.x * 4;
    float4 a = *(const float4*)(p0 + c);
    float4 b = *(const float4*)(p1 + c);
    float4 va = *(const float4*)(ba + c);
    float4 vb = *(const float4*)(bb + c);
    float4 o;
    o.x = 0.5f * (a.x + b.x + va.x + vb.x);
    o.y = 0.5f * (a.y + b.y + va.y + vb.y);
    o.z = 0.5f * (a.z + b.z + va.z + vb.z);
    o.w = 0.5f * (a.w + b.w + va.w + vb.w);
    *(float4*)(out + (size_t)t * D_DIM + c) = o;
}

// ---------------- launch ----------------
extern "C" void kernel_launch(void* const* d_in, const int* in_sizes, int n_in,
                              void* d_out, int out_size) {
    const float* x  = (const float*)d_in[0];
    const float* W1 = (const float*)d_in[1];
    const float* b1 = (const float*)d_in[2];
    const float* W2 = (const float*)d_in[3];
    const float* b2 = (const float*)d_in[4];
    float* out = (float*)d_out;

    int T = in_sizes[0] / D_DIM;
    if (T > T_MAX) T = T_MAX;

    zero_cnt_kernel<<<1, 32>>>();
    route_kernel<<<(T + 255) / 256, 256>>>(x, T);
    tilemap_kernel<<<1, 32>>>();
    convertA_kernel<<<dim3(MAX_TILES, 4), 256>>>(x);
    convertW_kernel<1><<<dim3(DFF / 32, D_DIM / 64, NE), dim3(32, 8)>>>(W1);
    convertW_kernel<2><<<dim3(D_DIM / 32, DFF / 64, NE), dim3(32, 8)>>>(W2);
    moe_gemm_hmma<D_DIM, 1, DFF><<<dim3(DFF / BN, MAX_TILES), 256>>>(b1);
    moe_gemm_hmma<DFF, 2, D_DIM><<<dim3(D_DIM / BN, MAX_TILES), 256>>>(b1);
    combine_kernel<<<T, 256>>>(x, b2, out);
}